// round 12
// baseline (speedup 1.0000x reference)
#include <cuda_runtime.h>
#include <cuda_fp16.h>
#include <cstdint>

#define RES    300
#define NCOMP  48
#define PCH    64
#define NFEAT  27
#define KTOT   144
#define NPTS_BLK 192
#define THREADS  384
#define NBUCK  4096

#define FROWB  304
#define F_OFF    0
#define F_BYTES  (NPTS_BLK * FROWB)         // 58368
#define WH_OFF   F_BYTES
#define WHROWB 336
#define WH_BYTES (32 * WHROWB)              // 10752
#define XYZ_OFF  (WH_OFF + WH_BYTES)        // 69120
#define XYZ_BYTES (NPTS_BLK * 3 * 4)        // 2304
#define PIDX_OFF (XYZ_OFF + XYZ_BYTES)      // 71424
#define PIDX_BYTES (NPTS_BLK * 4)           // 768
#define SMEM_DYN (PIDX_OFF + PIDX_BYTES)    // 72192 -> 3 CTAs/SM (216.5KB)
#define OSTRIDE  120

// Scratch
__device__ __align__(128) __half g_planesH[3u * RES * RES * PCH];
__device__ __align__(128) __half g_linesH [3u * RES * PCH];
__device__ int g_hist[NBUCK];
__device__ int g_cursor[NBUCK];
__device__ int g_perm[1100000];

// ---------------------------------------------------------------------------
__device__ __forceinline__ int bucket_key(float p0, float p1, float p2) {
    const int c0 = min(15, max(0, (int)((p0 + 1.0f) * 8.0f)));
    const int c1 = min(15, max(0, (int)((p1 + 1.0f) * 8.0f)));
    const int c2 = min(15, max(0, (int)((p2 + 1.0f) * 8.0f)));
    return (c0 << 8) | (c1 << 4) | c2;
}

__global__ void zero_hist_kernel() {
    g_hist[blockIdx.x * 256 + threadIdx.x] = 0;
}

__global__ void hist_kernel(const float* __restrict__ xyz, int npts) {
    const int n = blockIdx.x * 256 + threadIdx.x;
    if (n >= npts) return;
    atomicAdd(&g_hist[bucket_key(xyz[3*n], xyz[3*n+1], xyz[3*n+2])], 1);
}

// single block, 1024 threads, 4 bins each: exclusive scan of g_hist -> g_cursor
__global__ void scan_kernel() {
    __shared__ int ssum[1024];
    const int t = threadIdx.x;
    int v[4];
    int s = 0;
    #pragma unroll
    for (int q = 0; q < 4; q++) { v[q] = g_hist[t * 4 + q]; s += v[q]; }
    ssum[t] = s;
    __syncthreads();
    // Hillis-Steele inclusive scan over 1024 partial sums
    #pragma unroll
    for (int d = 1; d < 1024; d <<= 1) {
        int add = (t >= d) ? ssum[t - d] : 0;
        __syncthreads();
        ssum[t] += add;
        __syncthreads();
    }
    int run = (t > 0) ? ssum[t - 1] : 0;   // exclusive prefix of this thread's group
    #pragma unroll
    for (int q = 0; q < 4; q++) { g_cursor[t * 4 + q] = run; run += v[q]; }
}

__global__ void scatter_kernel(const float* __restrict__ xyz, int npts) {
    const int n = blockIdx.x * 256 + threadIdx.x;
    if (n >= npts) return;
    const int slot = atomicAdd(&g_cursor[bucket_key(xyz[3*n], xyz[3*n+1], xyz[3*n+2])], 1);
    g_perm[slot] = n;
}

// ---------------------------------------------------------------------------
__global__ void transpose_planes_kernel(const float* __restrict__ planes) {
    __shared__ float tile[NCOMP][33];
    const int i  = blockIdx.z;
    const int y  = blockIdx.y;
    const int xt = blockIdx.x * 32;
    const int t  = threadIdx.x;
    const int tx = t & 31;
    const int tc = t >> 5;
    const int x  = xt + tx;
    #pragma unroll
    for (int r = 0; r < 6; r++) {
        const int c = tc + 8 * r;
        if (x < RES)
            tile[c][tx] = planes[(((size_t)i * NCOMP + c) * RES + y) * RES + x];
    }
    __syncthreads();
    const int nx = min(32, RES - xt);
    __half* outb = g_planesH + (((size_t)i * RES + y) * RES + xt) * PCH;
    for (int e = t; e < nx * NCOMP; e += 256) {
        const int xl = e / NCOMP;
        const int c  = e - xl * NCOMP;
        outb[(size_t)xl * PCH + c] = __float2half(tile[c][xl]);
    }
}

__global__ void transpose_lines_kernel(const float* __restrict__ lines) {
    const int e = blockIdx.x * 256 + threadIdx.x;
    if (e >= 3 * RES * NCOMP) return;
    const int c  = e % NCOMP;
    const int ir = e / NCOMP;
    const int r  = ir % RES;
    const int i  = ir / RES;
    g_linesH[(size_t)ir * PCH + c] = __float2half(lines[((size_t)i * NCOMP + c) * RES + r]);
}

// ---------------------------------------------------------------------------
__device__ __forceinline__ uint32_t smem_u32(const void* p) {
    uint32_t a;
    asm("{ .reg .u64 t; cvta.to.shared.u64 t, %1; cvt.u32.u64 %0, t; }"
        : "=r"(a) : "l"(p));
    return a;
}
__device__ __forceinline__ float2 h2f(uint32_t u) {
    return __half22float2(*reinterpret_cast<const __half2*>(&u));
}
__device__ __forceinline__ uint32_t f2h2(float lo, float hi) {
    uint32_t r;
    asm("cvt.rn.f16x2.f32 %0, %1, %2;" : "=r"(r) : "f"(hi), "f"(lo));
    return r;
}
__device__ __forceinline__ void ldsm_x4(uint32_t& r0, uint32_t& r1,
                                        uint32_t& r2, uint32_t& r3, uint32_t addr) {
    asm volatile("ldmatrix.sync.aligned.m8n8.x4.shared.b16 {%0,%1,%2,%3}, [%4];"
                 : "=r"(r0), "=r"(r1), "=r"(r2), "=r"(r3) : "r"(addr));
}
__device__ __forceinline__ void mma16816(float* c,
                                         uint32_t a0, uint32_t a1, uint32_t a2, uint32_t a3,
                                         uint32_t b0, uint32_t b1) {
    asm volatile("mma.sync.aligned.m16n8k16.row.col.f32.f16.f16.f32 "
                 "{%0,%1,%2,%3}, {%4,%5,%6,%7}, {%8,%9}, {%0,%1,%2,%3};"
                 : "+f"(c[0]), "+f"(c[1]), "+f"(c[2]), "+f"(c[3])
                 : "r"(a0), "r"(a1), "r"(a2), "r"(a3), "r"(b0), "r"(b1));
}

// ---------------------------------------------------------------------------
__global__ __launch_bounds__(THREADS, 3)
void tvm_main_kernel(const float* __restrict__ xyz,
                     const float* __restrict__ basisW,
                     float* __restrict__ out,
                     int npts) {
    extern __shared__ char sm[];
    float* sXYZ = reinterpret_cast<float*>(sm + XYZ_OFF);
    int*   sPid = reinterpret_cast<int*>(sm + PIDX_OFF);
    const uint32_t sbase = smem_u32(sm);

    const int tid  = threadIdx.x;
    const int base = blockIdx.x * NPTS_BLK;

    // Stage W as fp16 [n=0..31][k=0..143], rows 27-31 zero.
    for (int e = tid; e < WH_BYTES / 16; e += THREADS)
        *reinterpret_cast<uint4*>(sm + WH_OFF + e * 16) = make_uint4(0, 0, 0, 0);
    // permutation indices for this block
    if (tid < NPTS_BLK)
        sPid[tid] = g_perm[min(base + tid, npts - 1)];
    __syncthreads();
    for (int e = tid; e < NFEAT * KTOT; e += THREADS) {
        const int n = e / KTOT;
        const int k = e - n * KTOT;
        *reinterpret_cast<__half*>(sm + WH_OFF + n * WHROWB + k * 2) =
            __float2half(basisW[e]);
    }
    for (int e = tid; e < NPTS_BLK * 3; e += THREADS) {
        const int p = e / 3;
        const int c = e - p * 3;
        sXYZ[e] = xyz[(size_t)sPid[p] * 3 + c];
    }
    __syncthreads();

    // ---------------- Phase 1: gather + interp ----------------
    #pragma unroll 1
    for (int it = 0; it < 3; it++) {
        const int s   = tid + it * THREADS;
        const int p   = s / 6;
        const int c16 = s - p * 6;
        const int co  = c16 * 8;

        const float p0 = sXYZ[p * 3 + 0];
        const float p1 = sXYZ[p * 3 + 1];
        const float p2 = sXYZ[p * 3 + 2];

        #pragma unroll 1
        for (int i = 0; i < 3; i++) {
            const float gx = (i == 2) ? p1 : p2;
            const float gy = (i == 0) ? p1 : p0;
            const float gz = (i == 0) ? p0 : ((i == 1) ? p1 : p2);

            const float sc = 0.5f * (float)(RES - 1);
            const float x = (gx + 1.0f) * sc, y = (gy + 1.0f) * sc, z = (gz + 1.0f) * sc;
            const float xf = floorf(x), yf = floorf(y), zf = floorf(z);
            const float wx = x - xf, wy = y - yf, wz = z - zf;
            const int x0 = min(max((int)xf, 0), RES - 1); const int x1 = min(x0 + 1, RES - 1);
            const int y0 = min(max((int)yf, 0), RES - 1); const int y1 = min(y0 + 1, RES - 1);
            const int z0 = min(max((int)zf, 0), RES - 1); const int z1 = min(z0 + 1, RES - 1);
            const float w00 = (1.0f - wx) * (1.0f - wy);
            const float w01 = wx * (1.0f - wy);
            const float w10 = (1.0f - wx) * wy;
            const float w11 = wx * wy;
            const float lw0 = 1.0f - wz, lw1 = wz;

            const __half* P = g_planesH + (size_t)i * (RES * RES * PCH);
            const __half* L = g_linesH  + (size_t)i * (RES * PCH);
            const uint4 t00 = *(const uint4*)(P + ((size_t)y0 * RES + x0) * PCH + co);
            const uint4 t01 = *(const uint4*)(P + ((size_t)y0 * RES + x1) * PCH + co);
            const uint4 t10 = *(const uint4*)(P + ((size_t)y1 * RES + x0) * PCH + co);
            const uint4 t11 = *(const uint4*)(P + ((size_t)y1 * RES + x1) * PCH + co);
            const uint4 tL0 = *(const uint4*)(L + (size_t)z0 * PCH + co);
            const uint4 tL1 = *(const uint4*)(L + (size_t)z1 * PCH + co);

            const uint32_t* a00 = &t00.x; const uint32_t* a01 = &t01.x;
            const uint32_t* a10 = &t10.x; const uint32_t* a11 = &t11.x;
            const uint32_t* aL0 = &tL0.x; const uint32_t* aL1 = &tL1.x;
            uint32_t fw[4];
            #pragma unroll
            for (int w = 0; w < 4; w++) {
                const float2 v00 = h2f(a00[w]), v01 = h2f(a01[w]);
                const float2 v10 = h2f(a10[w]), v11 = h2f(a11[w]);
                const float2 L0  = h2f(aL0[w]), L1  = h2f(aL1[w]);
                const float pf0 = w00*v00.x + w01*v01.x + w10*v10.x + w11*v11.x;
                const float pf1 = w00*v00.y + w01*v01.y + w10*v10.y + w11*v11.y;
                const float lf0 = lw0*L0.x + lw1*L1.x;
                const float lf1 = lw0*L0.y + lw1*L1.y;
                fw[w] = f2h2(pf0 * lf0, pf1 * lf1);
            }
            *reinterpret_cast<uint4*>(sm + F_OFF + (size_t)p * FROWB + (i * NCOMP + co) * 2) =
                make_uint4(fw[0], fw[1], fw[2], fw[3]);
        }
    }
    __syncthreads();

    // ---------------- Phase 2: HMMA matvec ----------------
    const int wid  = tid >> 5;
    const int lane = tid & 31;
    const int l16  = lane & 15;
    const int g    = lane >> 3;

    const uint32_t a_addr = sbase + F_OFF
        + (uint32_t)(16 * wid + l16) * FROWB + (uint32_t)(lane >> 4) * 16;
    const uint32_t b_addr = sbase + WH_OFF
        + (uint32_t)((g & 2) * 4 + (lane & 7)) * WHROWB + (uint32_t)(g & 1) * 16;

    float c[4][4];
    #pragma unroll
    for (int nt = 0; nt < 4; nt++)
        #pragma unroll
        for (int q = 0; q < 4; q++) c[nt][q] = 0.0f;

    #pragma unroll
    for (int ks = 0; ks < 9; ks++) {
        uint32_t a0, a1, a2, a3;
        ldsm_x4(a0, a1, a2, a3, a_addr + ks * 32);
        #pragma unroll
        for (int ntp = 0; ntp < 2; ntp++) {
            uint32_t b0, b1, b2, b3;
            ldsm_x4(b0, b1, b2, b3, b_addr + (uint32_t)ntp * (16 * WHROWB) + ks * 32);
            mma16816(c[2 * ntp],     a0, a1, a2, a3, b0, b1);
            mma16816(c[2 * ntp + 1], a0, a1, a2, a3, b2, b3);
        }
    }
    __syncthreads();

    // Epilogue: stage D rows at OSTRIDE-padded rows.
    {
        const int gq = lane >> 2;
        const int t  = lane & 3;
        char* stg = sm + F_OFF;
        #pragma unroll
        for (int nt = 0; nt < 4; nt++) {
            const int j0 = nt * 8 + 2 * t;
            if (j0 < 30) {
                *reinterpret_cast<float2*>(stg + (size_t)(16 * wid + gq) * OSTRIDE + j0 * 4) =
                    make_float2(c[nt][0], c[nt][1]);
                *reinterpret_cast<float2*>(stg + (size_t)(16 * wid + gq + 8) * OSTRIDE + j0 * 4) =
                    make_float2(c[nt][2], c[nt][3]);
            }
        }
    }
    __syncthreads();

    // store: per-point contiguous rows at permuted destinations
    for (int e = tid; e < NPTS_BLK * NFEAT; e += THREADS) {
        const int pt = e / NFEAT;
        const int j  = e - pt * NFEAT;
        if (base + pt < npts)
            out[(size_t)sPid[pt] * NFEAT + j] =
                *reinterpret_cast<const float*>(sm + F_OFF + (size_t)pt * OSTRIDE + j * 4);
    }
}

// ---------------------------------------------------------------------------
extern "C" void kernel_launch(void* const* d_in, const int* in_sizes, int n_in,
                              void* d_out, int out_size) {
    const float* xyz    = (const float*)d_in[0];
    const float* planes = (const float*)d_in[1];
    const float* lines  = (const float*)d_in[2];
    const float* basisW = (const float*)d_in[3];
    float* out = (float*)d_out;
    const int npts = in_sizes[0] / 3;

    cudaFuncSetAttribute(tvm_main_kernel,
                         cudaFuncAttributeMaxDynamicSharedMemorySize, SMEM_DYN);

    // sort prologue
    zero_hist_kernel<<<NBUCK / 256, 256>>>();
    hist_kernel<<<(npts + 255) / 256, 256>>>(xyz, npts);
    scan_kernel<<<1, 1024>>>();
    scatter_kernel<<<(npts + 255) / 256, 256>>>(xyz, npts);

    dim3 tg((RES + 31) / 32, RES, 3);
    transpose_planes_kernel<<<tg, 256>>>(planes);
    transpose_lines_kernel<<<(3 * RES * NCOMP + 255) / 256, 256>>>(lines);
    const int nblk = (npts + NPTS_BLK - 1) / NPTS_BLK;
    tvm_main_kernel<<<nblk, THREADS, SMEM_DYN>>>(xyz, basisW, out, npts);
}

// round 13
// speedup vs baseline: 1.3043x; 1.3043x over previous
#include <cuda_runtime.h>
#include <cuda_fp16.h>
#include <cstdint>

#define RES    300
#define NCOMP  48
#define PCH    64                           // padded channel stride (128B rows)
#define NFEAT  27
#define KTOT   144
#define NPTS_BLK 192
#define THREADS  384

#define FROWB  304
#define F_OFF    0
#define F_BYTES  (NPTS_BLK * FROWB)         // 58368
#define WH_OFF   F_BYTES
#define WHROWB 336
#define WH_BYTES (32 * WHROWB)              // 10752
#define XYZ_OFF  (WH_OFF + WH_BYTES)        // 69120
#define XYZ_BYTES (NPTS_BLK * 3 * 4)        // 2304
#define SMEM_DYN (XYZ_OFF + XYZ_BYTES)      // 71424 -> 3 CTAs/SM
#define OSTRIDE  120

// Scratch: channel-last transposed fp16 copies, 64-ch padded rows.
__device__ __align__(128) __half g_planesH[3u * RES * RES * PCH];
__device__ __align__(128) __half g_linesH [3u * RES * PCH];

// ---------------------------------------------------------------------------
__global__ void transpose_planes_kernel(const float* __restrict__ planes) {
    __shared__ float tile[NCOMP][33];
    const int i  = blockIdx.z;
    const int y  = blockIdx.y;
    const int xt = blockIdx.x * 32;
    const int t  = threadIdx.x;
    const int tx = t & 31;
    const int tc = t >> 5;
    const int x  = xt + tx;
    #pragma unroll
    for (int r = 0; r < 6; r++) {
        const int c = tc + 8 * r;
        if (x < RES)
            tile[c][tx] = planes[(((size_t)i * NCOMP + c) * RES + y) * RES + x];
    }
    __syncthreads();
    const int nx = min(32, RES - xt);
    __half* outb = g_planesH + (((size_t)i * RES + y) * RES + xt) * PCH;
    for (int e = t; e < nx * NCOMP; e += 256) {
        const int xl = e / NCOMP;
        const int c  = e - xl * NCOMP;
        outb[(size_t)xl * PCH + c] = __float2half(tile[c][xl]);
    }
}

__global__ void transpose_lines_kernel(const float* __restrict__ lines) {
    const int e = blockIdx.x * 256 + threadIdx.x;
    if (e >= 3 * RES * NCOMP) return;
    const int c  = e % NCOMP;
    const int ir = e / NCOMP;
    const int r  = ir % RES;
    const int i  = ir / RES;
    g_linesH[(size_t)ir * PCH + c] = __float2half(lines[((size_t)i * NCOMP + c) * RES + r]);
}

// ---------------------------------------------------------------------------
__device__ __forceinline__ uint32_t smem_u32(const void* p) {
    uint32_t a;
    asm("{ .reg .u64 t; cvta.to.shared.u64 t, %1; cvt.u32.u64 %0, t; }"
        : "=r"(a) : "l"(p));
    return a;
}
__device__ __forceinline__ __half2 uh2(uint32_t u) {
    return *reinterpret_cast<const __half2*>(&u);
}
__device__ __forceinline__ uint32_t h2u(__half2 h) {
    return *reinterpret_cast<const uint32_t*>(&h);
}
__device__ __forceinline__ void ldsm_x4(uint32_t& r0, uint32_t& r1,
                                        uint32_t& r2, uint32_t& r3, uint32_t addr) {
    asm volatile("ldmatrix.sync.aligned.m8n8.x4.shared.b16 {%0,%1,%2,%3}, [%4];"
                 : "=r"(r0), "=r"(r1), "=r"(r2), "=r"(r3) : "r"(addr));
}
__device__ __forceinline__ void mma16816(float* c,
                                         uint32_t a0, uint32_t a1, uint32_t a2, uint32_t a3,
                                         uint32_t b0, uint32_t b1) {
    asm volatile("mma.sync.aligned.m16n8k16.row.col.f32.f16.f16.f32 "
                 "{%0,%1,%2,%3}, {%4,%5,%6,%7}, {%8,%9}, {%0,%1,%2,%3};"
                 : "+f"(c[0]), "+f"(c[1]), "+f"(c[2]), "+f"(c[3])
                 : "r"(a0), "r"(a1), "r"(a2), "r"(a3), "r"(b0), "r"(b1));
}

// ---------------------------------------------------------------------------
// Main: phase1 = 6-lane cooperative gather + NATIVE fp16 (HFMA2) interp;
//       phase2 = HMMA matvec.
// ---------------------------------------------------------------------------
__global__ __launch_bounds__(THREADS, 3)
void tvm_main_kernel(const float* __restrict__ xyz,
                     const float* __restrict__ basisW,
                     float* __restrict__ out,
                     int npts) {
    extern __shared__ char sm[];
    float* sXYZ = reinterpret_cast<float*>(sm + XYZ_OFF);
    const uint32_t sbase = smem_u32(sm);

    const int tid  = threadIdx.x;
    const int base = blockIdx.x * NPTS_BLK;

    // Stage W as fp16 [n=0..31][k=0..143], rows 27-31 zero.
    for (int e = tid; e < WH_BYTES / 16; e += THREADS)
        *reinterpret_cast<uint4*>(sm + WH_OFF + e * 16) = make_uint4(0, 0, 0, 0);
    __syncthreads();
    for (int e = tid; e < NFEAT * KTOT; e += THREADS) {
        const int n = e / KTOT;
        const int k = e - n * KTOT;
        *reinterpret_cast<__half*>(sm + WH_OFF + n * WHROWB + k * 2) =
            __float2half(basisW[e]);
    }
    for (int e = tid; e < NPTS_BLK * 3; e += THREADS) {
        const int p = e / 3;
        const int c = e - p * 3;
        sXYZ[e] = xyz[(size_t)min(base + p, npts - 1) * 3 + c];
    }
    __syncthreads();

    // ---------------- Phase 1: gather + fp16 interp ----------------
    #pragma unroll 1
    for (int it = 0; it < 3; it++) {
        const int s   = tid + it * THREADS;
        const int p   = s / 6;
        const int c16 = s - p * 6;
        const int co  = c16 * 8;

        const float p0 = sXYZ[p * 3 + 0];
        const float p1 = sXYZ[p * 3 + 1];
        const float p2 = sXYZ[p * 3 + 2];

        #pragma unroll 1
        for (int i = 0; i < 3; i++) {
            const float gx = (i == 2) ? p1 : p2;
            const float gy = (i == 0) ? p1 : p0;
            const float gz = (i == 0) ? p0 : ((i == 1) ? p1 : p2);

            const float sc = 0.5f * (float)(RES - 1);
            const float x = (gx + 1.0f) * sc, y = (gy + 1.0f) * sc, z = (gz + 1.0f) * sc;
            const float xf = floorf(x), yf = floorf(y), zf = floorf(z);
            const float wx = x - xf, wy = y - yf, wz = z - zf;
            const int x0 = min(max((int)xf, 0), RES - 1); const int x1 = min(x0 + 1, RES - 1);
            const int y0 = min(max((int)yf, 0), RES - 1); const int y1 = min(y0 + 1, RES - 1);
            const int z0 = min(max((int)zf, 0), RES - 1); const int z1 = min(z0 + 1, RES - 1);

            // broadcast weights to half2 (1 cvt each)
            const __half2 w00h = __float2half2_rn((1.0f - wx) * (1.0f - wy));
            const __half2 w01h = __float2half2_rn(wx * (1.0f - wy));
            const __half2 w10h = __float2half2_rn((1.0f - wx) * wy);
            const __half2 w11h = __float2half2_rn(wx * wy);
            const __half2 lw0h = __float2half2_rn(1.0f - wz);
            const __half2 lw1h = __float2half2_rn(wz);

            const __half* P = g_planesH + (size_t)i * (RES * RES * PCH);
            const __half* L = g_linesH  + (size_t)i * (RES * PCH);
            const uint4 t00 = *(const uint4*)(P + ((size_t)y0 * RES + x0) * PCH + co);
            const uint4 t01 = *(const uint4*)(P + ((size_t)y0 * RES + x1) * PCH + co);
            const uint4 t10 = *(const uint4*)(P + ((size_t)y1 * RES + x0) * PCH + co);
            const uint4 t11 = *(const uint4*)(P + ((size_t)y1 * RES + x1) * PCH + co);
            const uint4 tL0 = *(const uint4*)(L + (size_t)z0 * PCH + co);
            const uint4 tL1 = *(const uint4*)(L + (size_t)z1 * PCH + co);

            const uint32_t* a00 = &t00.x; const uint32_t* a01 = &t01.x;
            const uint32_t* a10 = &t10.x; const uint32_t* a11 = &t11.x;
            const uint32_t* aL0 = &tL0.x; const uint32_t* aL1 = &tL1.x;
            uint32_t fw[4];
            #pragma unroll
            for (int w = 0; w < 4; w++) {          // 2 channels per iter, all HFMA2
                __half2 pf = __hmul2(w00h, uh2(a00[w]));
                pf = __hfma2(w01h, uh2(a01[w]), pf);
                pf = __hfma2(w10h, uh2(a10[w]), pf);
                pf = __hfma2(w11h, uh2(a11[w]), pf);
                __half2 lf = __hmul2(lw0h, uh2(aL0[w]));
                lf = __hfma2(lw1h, uh2(aL1[w]), lf);
                fw[w] = h2u(__hmul2(pf, lf));
            }
            *reinterpret_cast<uint4*>(sm + F_OFF + (size_t)p * FROWB + (i * NCOMP + co) * 2) =
                make_uint4(fw[0], fw[1], fw[2], fw[3]);
        }
    }
    __syncthreads();

    // ---------------- Phase 2: HMMA matvec ----------------
    const int wid  = tid >> 5;
    const int lane = tid & 31;
    const int l16  = lane & 15;
    const int g    = lane >> 3;

    const uint32_t a_addr = sbase + F_OFF
        + (uint32_t)(16 * wid + l16) * FROWB + (uint32_t)(lane >> 4) * 16;
    const uint32_t b_addr = sbase + WH_OFF
        + (uint32_t)((g & 2) * 4 + (lane & 7)) * WHROWB + (uint32_t)(g & 1) * 16;

    float c[4][4];
    #pragma unroll
    for (int nt = 0; nt < 4; nt++)
        #pragma unroll
        for (int q = 0; q < 4; q++) c[nt][q] = 0.0f;

    #pragma unroll
    for (int ks = 0; ks < 9; ks++) {
        uint32_t a0, a1, a2, a3;
        ldsm_x4(a0, a1, a2, a3, a_addr + ks * 32);
        #pragma unroll
        for (int ntp = 0; ntp < 2; ntp++) {
            uint32_t b0, b1, b2, b3;
            ldsm_x4(b0, b1, b2, b3, b_addr + (uint32_t)ntp * (16 * WHROWB) + ks * 32);
            mma16816(c[2 * ntp],     a0, a1, a2, a3, b0, b1);
            mma16816(c[2 * ntp + 1], a0, a1, a2, a3, b2, b3);
        }
    }
    __syncthreads();

    // Epilogue: stage D rows at OSTRIDE-padded rows.
    {
        const int gq = lane >> 2;
        const int t  = lane & 3;
        char* stg = sm + F_OFF;
        #pragma unroll
        for (int nt = 0; nt < 4; nt++) {
            const int j0 = nt * 8 + 2 * t;
            if (j0 < 30) {
                *reinterpret_cast<float2*>(stg + (size_t)(16 * wid + gq) * OSTRIDE + j0 * 4) =
                    make_float2(c[nt][0], c[nt][1]);
                *reinterpret_cast<float2*>(stg + (size_t)(16 * wid + gq + 8) * OSTRIDE + j0 * 4) =
                    make_float2(c[nt][2], c[nt][3]);
            }
        }
    }
    __syncthreads();

    // coalesced store
    for (int e = tid; e < NPTS_BLK * NFEAT; e += THREADS) {
        const int pt = e / NFEAT;
        const int j  = e - pt * NFEAT;
        if (base + pt < npts)
            out[(size_t)(base + pt) * NFEAT + j] =
                *reinterpret_cast<const float*>(sm + F_OFF + (size_t)pt * OSTRIDE + j * 4);
    }
}

// ---------------------------------------------------------------------------
extern "C" void kernel_launch(void* const* d_in, const int* in_sizes, int n_in,
                              void* d_out, int out_size) {
    const float* xyz    = (const float*)d_in[0];
    const float* planes = (const float*)d_in[1];
    const float* lines  = (const float*)d_in[2];
    const float* basisW = (const float*)d_in[3];
    float* out = (float*)d_out;
    const int npts = in_sizes[0] / 3;

    cudaFuncSetAttribute(tvm_main_kernel,
                         cudaFuncAttributeMaxDynamicSharedMemorySize, SMEM_DYN);

    dim3 tg((RES + 31) / 32, RES, 3);
    transpose_planes_kernel<<<tg, 256>>>(planes);
    transpose_lines_kernel<<<(3 * RES * NCOMP + 255) / 256, 256>>>(lines);
    const int nblk = (npts + NPTS_BLK - 1) / NPTS_BLK;
    tvm_main_kernel<<<nblk, THREADS, SMEM_DYN>>>(xyz, basisW, out, npts);
}